// round 1
// baseline (speedup 1.0000x reference)
#include <cuda_runtime.h>

static constexpr int B_  = 2;
static constexpr int T_  = 2048;
static constexpr int C_  = 1024;
static constexpr int H_  = 16;
static constexpr int HD_ = 64;
static constexpr int C3_ = 3 * C_;

// Scratch (no allocation allowed) — ~67 MB total.
__device__ float g_qkv[(size_t)B_ * T_ * C3_];
__device__ float g_y[(size_t)B_ * T_ * C_];

// ---------------------------------------------------------------------------
// SGEMM (NT): C[m][n] = sum_k A[m][k] * Bw[n][k]
// 128x128 tile, BK=8, 256 threads, 8x8 per thread.
// Transposed smem tiles [BK][BM+4] -> conflict-free stores, broadcast/vector reads.
// ---------------------------------------------------------------------------
__global__ __launch_bounds__(256)
void sgemm_nt(const float* __restrict__ A, const float* __restrict__ Bw,
              float* __restrict__ Cout, int M, int N, int K)
{
    constexpr int BM = 128, BN = 128, BK = 8;
    __shared__ float As[BK][BM + 4];
    __shared__ float Bs[BK][BN + 4];
    const int tid = threadIdx.x;
    const int m0 = blockIdx.y * BM;
    const int n0 = blockIdx.x * BN;
    const int wr = (tid >> 4) * 8;     // 16 row-groups of 8
    const int wc = (tid & 15) * 8;     // 16 col-groups of 8
    const int lr = tid >> 1;           // 0..127
    const int lk = (tid & 1) * 4;      // 0 or 4

    float acc[8][8];
#pragma unroll
    for (int i = 0; i < 8; i++)
#pragma unroll
        for (int j = 0; j < 8; j++) acc[i][j] = 0.f;

    const float* Ap = A + (size_t)(m0 + lr) * K + lk;
    const float* Bp = Bw + (size_t)(n0 + lr) * K + lk;

    for (int k0 = 0; k0 < K; k0 += BK) {
        float4 av = *reinterpret_cast<const float4*>(Ap + k0);
        float4 bv = *reinterpret_cast<const float4*>(Bp + k0);
        __syncthreads();
        As[lk + 0][lr] = av.x; As[lk + 1][lr] = av.y;
        As[lk + 2][lr] = av.z; As[lk + 3][lr] = av.w;
        Bs[lk + 0][lr] = bv.x; Bs[lk + 1][lr] = bv.y;
        Bs[lk + 2][lr] = bv.z; Bs[lk + 3][lr] = bv.w;
        __syncthreads();
#pragma unroll
        for (int k = 0; k < BK; k++) {
            float a[8], b[8];
#pragma unroll
            for (int i = 0; i < 8; i++) a[i] = As[k][wr + i];
#pragma unroll
            for (int j = 0; j < 8; j++) b[j] = Bs[k][wc + j];
#pragma unroll
            for (int i = 0; i < 8; i++)
#pragma unroll
                for (int j = 0; j < 8; j++) acc[i][j] += a[i] * b[j];
        }
    }
#pragma unroll
    for (int i = 0; i < 8; i++) {
        float* crow = Cout + (size_t)(m0 + wr + i) * N + n0 + wc;
#pragma unroll
        for (int j = 0; j < 8; j += 4) {
            float4 v = make_float4(acc[i][j], acc[i][j + 1], acc[i][j + 2], acc[i][j + 3]);
            *reinterpret_cast<float4*>(crow + j) = v;
        }
    }
}

// ---------------------------------------------------------------------------
// Fused per-head RMSNorm + RoPE, in-place on q and k slices of qkv.
// One warp per (b*t, head); lane l owns the rotation pair (2l, 2l+1).
// ---------------------------------------------------------------------------
__global__ __launch_bounds__(256)
void norm_rope(float* __restrict__ qkv, const float* __restrict__ cosT,
               const float* __restrict__ sinT, const float* __restrict__ qw,
               const float* __restrict__ kw)
{
    const int gw = (blockIdx.x * blockDim.x + threadIdx.x) >> 5;
    const int lane = threadIdx.x & 31;
    const int h = gw & (H_ - 1);
    const int bt = gw >> 4;
    const int t = bt & (T_ - 1);

    float* qp = qkv + (size_t)bt * C3_ + h * HD_;
    float* kp = qp + C_;
    const float c = cosT[t * (HD_ / 2) + lane];
    const float s = sinT[t * (HD_ / 2) + lane];

    {
        float2 v = *reinterpret_cast<float2*>(qp + 2 * lane);
        float ss = v.x * v.x + v.y * v.y;
#pragma unroll
        for (int off = 16; off > 0; off >>= 1)
            ss += __shfl_xor_sync(0xffffffffu, ss, off);
        float rms = rsqrtf(ss * (1.f / HD_) + 1e-6f);
        float x0 = v.x * rms * qw[2 * lane];
        float x1 = v.y * rms * qw[2 * lane + 1];
        v.x = x0 * c - x1 * s;
        v.y = x0 * s + x1 * c;
        *reinterpret_cast<float2*>(qp + 2 * lane) = v;
    }
    {
        float2 v = *reinterpret_cast<float2*>(kp + 2 * lane);
        float ss = v.x * v.x + v.y * v.y;
#pragma unroll
        for (int off = 16; off > 0; off >>= 1)
            ss += __shfl_xor_sync(0xffffffffu, ss, off);
        float rms = rsqrtf(ss * (1.f / HD_) + 1e-6f);
        float x0 = v.x * rms * kw[2 * lane];
        float x1 = v.y * rms * kw[2 * lane + 1];
        v.x = x0 * c - x1 * s;
        v.y = x0 * s + x1 * c;
        *reinterpret_cast<float2*>(kp + 2 * lane) = v;
    }
}

// ---------------------------------------------------------------------------
// FP32 flash attention, causal. BQ=128 queries/block, BKV=64 keys/iter.
// 256 threads: 16x16 grid, each thread computes 8 rows x 4 cols.
// Dynamic smem: Qs[128][65] Ks[64][65] Vs[64][65] Ps[128][65] = 99840 B.
// ---------------------------------------------------------------------------
__global__ __launch_bounds__(256)
void flash_fwd(const float* __restrict__ qkv, float* __restrict__ y)
{
    constexpr int BQ = 128, BKV = 64, LD = HD_ + 1;
    extern __shared__ float sm[];
    float (*Qs)[LD]       = reinterpret_cast<float(*)[LD]>(sm);
    float (*Ks)[LD]       = reinterpret_cast<float(*)[LD]>(sm + BQ * LD);
    float (*Vs)[LD]       = reinterpret_cast<float(*)[LD]>(sm + (BQ + BKV) * LD);
    float (*Ps)[BKV + 1]  = reinterpret_cast<float(*)[BKV + 1]>(sm + (BQ + 2 * BKV) * LD);

    const int bh = blockIdx.y;               // b*H + h
    const int b = bh >> 4, h = bh & 15;
    const int q0 = (gridDim.x - 1 - blockIdx.x) * BQ;  // heavy tiles first

    const int tid = threadIdx.x;
    const int ty = tid >> 4;    // 0..15 -> rows ty*8..+8
    const int tx = tid & 15;    // 0..15 -> cols tx*4..+4

    const float* qbase = qkv + (size_t)b * T_ * C3_ + (size_t)h * HD_;
    const float* kbase = qbase + C_;
    const float* vbase = qbase + 2 * C_;

    // Load Q tile (rows q0..q0+127)
    for (int idx = tid; idx < BQ * (HD_ / 4); idx += 256) {
        int r = idx >> 4;
        int d4 = (idx & 15) * 4;
        float4 v = *reinterpret_cast<const float4*>(qbase + (size_t)(q0 + r) * C3_ + d4);
        Qs[r][d4 + 0] = v.x; Qs[r][d4 + 1] = v.y;
        Qs[r][d4 + 2] = v.z; Qs[r][d4 + 3] = v.w;
    }

    float o[8][4], m[8], l[8];
#pragma unroll
    for (int i = 0; i < 8; i++) {
        m[i] = -1e30f; l[i] = 0.f;
#pragma unroll
        for (int j = 0; j < 4; j++) o[i][j] = 0.f;
    }

    const int kv_end = q0 + BQ;
    for (int j0 = 0; j0 < kv_end; j0 += BKV) {
        __syncthreads();   // previous iter's reads of Ks/Vs/Ps done
        for (int idx = tid; idx < BKV * (HD_ / 4); idx += 256) {
            int r = idx >> 4;
            int d4 = (idx & 15) * 4;
            float4 kv4 = *reinterpret_cast<const float4*>(kbase + (size_t)(j0 + r) * C3_ + d4);
            Ks[r][d4 + 0] = kv4.x; Ks[r][d4 + 1] = kv4.y;
            Ks[r][d4 + 2] = kv4.z; Ks[r][d4 + 3] = kv4.w;
            float4 vv = *reinterpret_cast<const float4*>(vbase + (size_t)(j0 + r) * C3_ + d4);
            Vs[r][d4 + 0] = vv.x; Vs[r][d4 + 1] = vv.y;
            Vs[r][d4 + 2] = vv.z; Vs[r][d4 + 3] = vv.w;
        }
        __syncthreads();

        // S = (Q K^T) * scale
        float s[8][4];
#pragma unroll
        for (int i = 0; i < 8; i++)
#pragma unroll
            for (int j = 0; j < 4; j++) s[i][j] = 0.f;
#pragma unroll 8
        for (int d = 0; d < HD_; d++) {
            float a[8], bb[4];
#pragma unroll
            for (int i = 0; i < 8; i++) a[i] = Qs[ty * 8 + i][d];
#pragma unroll
            for (int j = 0; j < 4; j++) bb[j] = Ks[tx * 4 + j][d];
#pragma unroll
            for (int i = 0; i < 8; i++)
#pragma unroll
                for (int j = 0; j < 4; j++) s[i][j] += a[i] * bb[j];
        }
        const bool need_mask = (j0 + BKV - 1) > q0;
#pragma unroll
        for (int i = 0; i < 8; i++) {
            const int qi = q0 + ty * 8 + i;
#pragma unroll
            for (int j = 0; j < 4; j++) {
                float val = s[i][j] * 0.125f;   // 1/sqrt(64)
                if (need_mask && (j0 + tx * 4 + j) > qi) val = -1e30f;
                s[i][j] = val;
            }
        }

        // online softmax update (row groups of 16 lanes share rows)
#pragma unroll
        for (int i = 0; i < 8; i++) {
            float mx = fmaxf(fmaxf(s[i][0], s[i][1]), fmaxf(s[i][2], s[i][3]));
#pragma unroll
            for (int off = 8; off > 0; off >>= 1)
                mx = fmaxf(mx, __shfl_xor_sync(0xffffffffu, mx, off));
            const float mnew = fmaxf(m[i], mx);
            const float alpha = __expf(m[i] - mnew);
            float psum = 0.f;
#pragma unroll
            for (int j = 0; j < 4; j++) {
                float p = __expf(s[i][j] - mnew);
                s[i][j] = p;
                psum += p;
            }
#pragma unroll
            for (int off = 8; off > 0; off >>= 1)
                psum += __shfl_xor_sync(0xffffffffu, psum, off);
            l[i] = l[i] * alpha + psum;
            m[i] = mnew;
#pragma unroll
            for (int j = 0; j < 4; j++) o[i][j] *= alpha;
        }

        // stage P
#pragma unroll
        for (int i = 0; i < 8; i++)
#pragma unroll
            for (int j = 0; j < 4; j++)
                Ps[ty * 8 + i][tx * 4 + j] = s[i][j];
        __syncthreads();

        // O += P @ V   (thread: rows ty*8.., dcols tx*4..)
#pragma unroll 8
        for (int j = 0; j < BKV; j++) {
            float a[8], bb[4];
#pragma unroll
            for (int i = 0; i < 8; i++) a[i] = Ps[ty * 8 + i][j];
#pragma unroll
            for (int jj = 0; jj < 4; jj++) bb[jj] = Vs[j][tx * 4 + jj];
#pragma unroll
            for (int i = 0; i < 8; i++)
#pragma unroll
                for (int jj = 0; jj < 4; jj++) o[i][jj] += a[i] * bb[jj];
        }
    }

    // epilogue: y[b, q, h*64 + d] = o / l
    float* ybase = y + (size_t)b * T_ * C_ + (size_t)h * HD_;
#pragma unroll
    for (int i = 0; i < 8; i++) {
        const float inv = 1.0f / l[i];
        const size_t row = (size_t)(q0 + ty * 8 + i) * C_;
#pragma unroll
        for (int jj = 0; jj < 4; jj++)
            ybase[row + tx * 4 + jj] = o[i][jj] * inv;
    }
}

// ---------------------------------------------------------------------------
extern "C" void kernel_launch(void* const* d_in, const int* in_sizes, int n_in,
                              void* d_out, int out_size)
{
    const float* x      = (const float*)d_in[0];
    const float* fcos   = (const float*)d_in[1];
    const float* fsin   = (const float*)d_in[2];
    const float* w_attn = (const float*)d_in[3];
    const float* w_proj = (const float*)d_in[4];
    const float* qw     = (const float*)d_in[5];
    const float* kw     = (const float*)d_in[6];
    float* out = (float*)d_out;

    float* qkv = nullptr;
    float* yb = nullptr;
    cudaGetSymbolAddress((void**)&qkv, g_qkv);
    cudaGetSymbolAddress((void**)&yb, g_y);

    // 1) qkv = x @ w_attn^T           [4096,1024] x [3072,1024]^T
    dim3 g1(C3_ / 128, (B_ * T_) / 128);
    sgemm_nt<<<g1, 256>>>(x, w_attn, qkv, B_ * T_, C3_, C_);

    // 2) per-head RMSNorm + RoPE on q,k (in place)
    norm_rope<<<(B_ * T_ * H_) / 8, 256>>>(qkv, fcos, fsin, qw, kw);

    // 3) causal flash attention -> y
    const int flash_smem = (128 * 65 + 64 * 65 + 64 * 65 + 128 * 65) * (int)sizeof(float);
    cudaFuncSetAttribute(flash_fwd, cudaFuncAttributeMaxDynamicSharedMemorySize, flash_smem);
    dim3 g3(T_ / 128, B_ * H_);
    flash_fwd<<<g3, 256, flash_smem>>>(qkv, yb);

    // 4) out = y @ w_proj^T           [4096,1024] x [1024,1024]^T
    dim3 g4(C_ / 128, (B_ * T_) / 128);
    sgemm_nt<<<g4, 256>>>(yb, w_proj, out, B_ * T_, C_, C_);
}

// round 4
// speedup vs baseline: 1.5652x; 1.5652x over previous
#include <cuda_runtime.h>
#include <cuda_bf16.h>
#include <cstdint>
#include <cstddef>

static constexpr int B_  = 2;
static constexpr int T_  = 2048;
static constexpr int C_  = 1024;
static constexpr int H_  = 16;
static constexpr int HD_ = 64;
static constexpr int C3_ = 3 * C_;
static constexpr int M_  = B_ * T_;      // 4096

// ---------------------------------------------------------------------------
// Scratch (__device__ globals; no allocation allowed)
// ---------------------------------------------------------------------------
__device__ float g_qkv[(size_t)M_ * C3_];                 // 50 MB
__device__ float g_y[(size_t)M_ * C_];                    // 17 MB
__device__ __nv_bfloat16 g_xhi[(size_t)M_ * C_];
__device__ __nv_bfloat16 g_xlo[(size_t)M_ * C_];
__device__ __nv_bfloat16 g_wahi[(size_t)C3_ * C_];
__device__ __nv_bfloat16 g_walo[(size_t)C3_ * C_];
__device__ __nv_bfloat16 g_wphi[(size_t)C_ * C_];
__device__ __nv_bfloat16 g_wplo[(size_t)C_ * C_];
__device__ __nv_bfloat16 g_yhi[(size_t)M_ * C_];
__device__ __nv_bfloat16 g_ylo[(size_t)M_ * C_];

// ---------------------------------------------------------------------------
// Helpers (sm_80-level features only: cp.async, ldmatrix, mma.sync)
// ---------------------------------------------------------------------------
__device__ __forceinline__ uint32_t smem_u32(const void* p) {
    uint32_t a;
    asm("{ .reg .u64 t; cvta.to.shared.u64 t, %1; cvt.u32.u64 %0, t; }" : "=r"(a) : "l"(p));
    return a;
}
#define SWZ128(o) ((o) ^ (((o) >> 3) & 0x70))

__device__ __forceinline__ void cp_async16(uint32_t dst, const void* src) {
    asm volatile("cp.async.cg.shared.global [%0], [%1], 16;" :: "r"(dst), "l"(src));
}
__device__ __forceinline__ void ldsm4(uint32_t& r0, uint32_t& r1, uint32_t& r2, uint32_t& r3,
                                      uint32_t addr) {
    asm volatile("ldmatrix.sync.aligned.m8n8.x4.shared.b16 {%0,%1,%2,%3}, [%4];"
                 : "=r"(r0), "=r"(r1), "=r"(r2), "=r"(r3) : "r"(addr));
}
__device__ __forceinline__ void mma16816(float* c, const uint32_t* a, const uint32_t* b) {
    asm volatile(
        "mma.sync.aligned.m16n8k16.row.col.f32.bf16.bf16.f32 "
        "{%0,%1,%2,%3}, {%4,%5,%6,%7}, {%8,%9}, {%0,%1,%2,%3};"
        : "+f"(c[0]), "+f"(c[1]), "+f"(c[2]), "+f"(c[3])
        : "r"(a[0]), "r"(a[1]), "r"(a[2]), "r"(a[3]), "r"(b[0]), "r"(b[1]));
}

// ---------------------------------------------------------------------------
// Split fp32 -> (hi, lo) bf16
// ---------------------------------------------------------------------------
__global__ __launch_bounds__(256)
void split_f32(const float* __restrict__ in, __nv_bfloat16* __restrict__ hi,
               __nv_bfloat16* __restrict__ lo, int n4)
{
    int i = blockIdx.x * blockDim.x + threadIdx.x;
    if (i >= n4) return;
    float4 v = reinterpret_cast<const float4*>(in)[i];
    __nv_bfloat16 h0 = __float2bfloat16_rn(v.x);
    __nv_bfloat16 h1 = __float2bfloat16_rn(v.y);
    __nv_bfloat16 h2 = __float2bfloat16_rn(v.z);
    __nv_bfloat16 h3 = __float2bfloat16_rn(v.w);
    __nv_bfloat162 hh0 = __nv_bfloat162(h0, h1);
    __nv_bfloat162 hh1 = __nv_bfloat162(h2, h3);
    __nv_bfloat162 ll0 = __nv_bfloat162(__float2bfloat16_rn(v.x - __bfloat162float(h0)),
                                        __float2bfloat16_rn(v.y - __bfloat162float(h1)));
    __nv_bfloat162 ll1 = __nv_bfloat162(__float2bfloat16_rn(v.z - __bfloat162float(h2)),
                                        __float2bfloat16_rn(v.w - __bfloat162float(h3)));
    reinterpret_cast<__nv_bfloat162*>(hi)[2 * i]     = hh0;
    reinterpret_cast<__nv_bfloat162*>(hi)[2 * i + 1] = hh1;
    reinterpret_cast<__nv_bfloat162*>(lo)[2 * i]     = ll0;
    reinterpret_cast<__nv_bfloat162*>(lo)[2 * i + 1] = ll1;
}

// ---------------------------------------------------------------------------
// mma.sync split-bf16 GEMM (NT): C[m][n] = sum_k A[m][k]*B[n][k] (fp32-accurate)
// 3 accumulating passes: Ahi*Bhi + Ahi*Blo + Alo*Bhi
// 128x128 tile, BK=64, 8 warps (2x4, 64x32 each), cp.async double buffer,
// SW128-swizzled smem (128B rows), ldmatrix operand fetch.
// smem: 2 bufs x (A 16KB + B 16KB) = 64 KB.
// ---------------------------------------------------------------------------
static constexpr int GSMEM = 65536;

__global__ __launch_bounds__(256)
void gemm_mma_split(const __nv_bfloat16* __restrict__ Ahi,
                    const __nv_bfloat16* __restrict__ Alo,
                    const __nv_bfloat16* __restrict__ Bhi,
                    const __nv_bfloat16* __restrict__ Blo,
                    float* __restrict__ Cout, int N, int K)
{
    extern __shared__ char smem[];
    const uint32_t smem_base = smem_u32(smem);
    const int tid  = threadIdx.x;
    const int lane = tid & 31;
    const int wid  = tid >> 5;
    const int wr = (wid >> 2) * 64;       // warp row offset within tile (0 / 64)
    const int wc = (wid & 3) * 32;        // warp col offset (0/32/64/96)
    const int m0 = blockIdx.y * 128;
    const int n0 = blockIdx.x * 128;

    float acc[4][4][4];
#pragma unroll
    for (int mi = 0; mi < 4; mi++)
#pragma unroll
        for (int ni = 0; ni < 4; ni++)
#pragma unroll
            for (int e = 0; e < 4; e++) acc[mi][ni][e] = 0.f;

    const __nv_bfloat16* Aps[3] = { Ahi, Ahi, Alo };
    const __nv_bfloat16* Bps[3] = { Bhi, Blo, Bhi };
    const int KC = K >> 6;             // 64-wide chunks per pass
    const int NC = 3 * KC;

    auto load_chunk = [&](int cg) {
        const int pass = cg / KC;
        const int kc   = cg - pass * KC;
        const __nv_bfloat16* Ab = Aps[pass] + (size_t)m0 * K + kc * 64;
        const __nv_bfloat16* Bb = Bps[pass] + (size_t)n0 * K + kc * 64;
        const uint32_t As = smem_base + (cg & 1) * 16384;
        const uint32_t Bs = smem_base + 32768 + (cg & 1) * 16384;
#pragma unroll
        for (int i = 0; i < 4; i++) {
            const int u = tid + 256 * i;       // 0..1023
            const int row = u >> 3, ch = u & 7;
            cp_async16(As + SWZ128(row * 128 + ch * 16), Ab + (size_t)row * K + ch * 8);
            cp_async16(Bs + SWZ128(row * 128 + ch * 16), Bb + (size_t)row * K + ch * 8);
        }
        asm volatile("cp.async.commit_group;");
    };

    load_chunk(0);
    for (int cg = 0; cg < NC; cg++) {
        if (cg + 1 < NC) {
            load_chunk(cg + 1);
            asm volatile("cp.async.wait_group 1;");
        } else {
            asm volatile("cp.async.wait_group 0;");
        }
        __syncthreads();

        const uint32_t As = smem_base + (cg & 1) * 16384;
        const uint32_t Bs = smem_base + 32768 + (cg & 1) * 16384;
#pragma unroll
        for (int ks = 0; ks < 4; ks++) {
            const int k0 = ks * 16;
            uint32_t a[4][4], b[4][2];
#pragma unroll
            for (int mi = 0; mi < 4; mi++) {
                const uint32_t ad = As + SWZ128((wr + mi * 16 + (lane & 15)) * 128 +
                                                (k0 + (lane >> 4) * 8) * 2);
                ldsm4(a[mi][0], a[mi][1], a[mi][2], a[mi][3], ad);
            }
#pragma unroll
            for (int p = 0; p < 2; p++) {
                const int g = lane >> 3;
                const int r = wc + p * 16 + (g >> 1) * 8 + (lane & 7);
                const int cb = (k0 + (g & 1) * 8) * 2;
                const uint32_t bd = Bs + SWZ128(r * 128 + cb);
                ldsm4(b[2 * p][0], b[2 * p][1], b[2 * p + 1][0], b[2 * p + 1][1], bd);
            }
#pragma unroll
            for (int mi = 0; mi < 4; mi++)
#pragma unroll
                for (int ni = 0; ni < 4; ni++)
                    mma16816(acc[mi][ni], a[mi], b[ni]);
        }
        __syncthreads();
    }

    // epilogue: fragment -> gmem (float2 stores, 8B aligned)
#pragma unroll
    for (int mi = 0; mi < 4; mi++) {
        const int m = m0 + wr + mi * 16 + (lane >> 2);
#pragma unroll
        for (int ni = 0; ni < 4; ni++) {
            const int n = n0 + wc + ni * 8 + (lane & 3) * 2;
            *reinterpret_cast<float2*>(Cout + (size_t)m * N + n) =
                make_float2(acc[mi][ni][0], acc[mi][ni][1]);
            *reinterpret_cast<float2*>(Cout + (size_t)(m + 8) * N + n) =
                make_float2(acc[mi][ni][2], acc[mi][ni][3]);
        }
    }
}

// ---------------------------------------------------------------------------
// Fused per-head RMSNorm + RoPE
// ---------------------------------------------------------------------------
__global__ __launch_bounds__(256)
void norm_rope(float* __restrict__ qkv, const float* __restrict__ cosT,
               const float* __restrict__ sinT, const float* __restrict__ qw,
               const float* __restrict__ kw)
{
    const int gw = (blockIdx.x * blockDim.x + threadIdx.x) >> 5;
    const int lane = threadIdx.x & 31;
    const int h = gw & (H_ - 1);
    const int bt = gw >> 4;
    const int t = bt & (T_ - 1);

    float* qp = qkv + (size_t)bt * C3_ + h * HD_;
    float* kp = qp + C_;
    const float c = cosT[t * (HD_ / 2) + lane];
    const float s = sinT[t * (HD_ / 2) + lane];

    {
        float2 v = *reinterpret_cast<float2*>(qp + 2 * lane);
        float ss = v.x * v.x + v.y * v.y;
#pragma unroll
        for (int off = 16; off > 0; off >>= 1) ss += __shfl_xor_sync(0xffffffffu, ss, off);
        float rms = rsqrtf(ss * (1.f / HD_) + 1e-6f);
        float x0 = v.x * rms * qw[2 * lane];
        float x1 = v.y * rms * qw[2 * lane + 1];
        v.x = x0 * c - x1 * s;
        v.y = x0 * s + x1 * c;
        *reinterpret_cast<float2*>(qp + 2 * lane) = v;
    }
    {
        float2 v = *reinterpret_cast<float2*>(kp + 2 * lane);
        float ss = v.x * v.x + v.y * v.y;
#pragma unroll
        for (int off = 16; off > 0; off >>= 1) ss += __shfl_xor_sync(0xffffffffu, ss, off);
        float rms = rsqrtf(ss * (1.f / HD_) + 1e-6f);
        float x0 = v.x * rms * kw[2 * lane];
        float x1 = v.y * rms * kw[2 * lane + 1];
        v.x = x0 * c - x1 * s;
        v.y = x0 * s + x1 * c;
        *reinterpret_cast<float2*>(kp + 2 * lane) = v;
    }
}

// ---------------------------------------------------------------------------
// FP32 flash attention, causal (known-good from R1)
// ---------------------------------------------------------------------------
__global__ __launch_bounds__(256)
void flash_fwd(const float* __restrict__ qkv, float* __restrict__ y)
{
    constexpr int BQ = 128, BKV = 64, LD = HD_ + 1;
    extern __shared__ float sm[];
    float (*Qs)[LD]      = reinterpret_cast<float(*)[LD]>(sm);
    float (*Ks)[LD]      = reinterpret_cast<float(*)[LD]>(sm + BQ * LD);
    float (*Vs)[LD]      = reinterpret_cast<float(*)[LD]>(sm + (BQ + BKV) * LD);
    float (*Ps)[BKV + 1] = reinterpret_cast<float(*)[BKV + 1]>(sm + (BQ + 2 * BKV) * LD);

    const int bh = blockIdx.y;
    const int b = bh >> 4, h = bh & 15;
    const int q0 = (gridDim.x - 1 - blockIdx.x) * BQ;

    const int tid = threadIdx.x;
    const int ty = tid >> 4;
    const int tx = tid & 15;

    const float* qbase = qkv + (size_t)b * T_ * C3_ + (size_t)h * HD_;
    const float* kbase = qbase + C_;
    const float* vbase = qbase + 2 * C_;

    for (int idx = tid; idx < BQ * (HD_ / 4); idx += 256) {
        int r = idx >> 4;
        int d4 = (idx & 15) * 4;
        float4 v = *reinterpret_cast<const float4*>(qbase + (size_t)(q0 + r) * C3_ + d4);
        Qs[r][d4 + 0] = v.x; Qs[r][d4 + 1] = v.y;
        Qs[r][d4 + 2] = v.z; Qs[r][d4 + 3] = v.w;
    }

    float o[8][4], m[8], l[8];
#pragma unroll
    for (int i = 0; i < 8; i++) {
        m[i] = -1e30f; l[i] = 0.f;
#pragma unroll
        for (int j = 0; j < 4; j++) o[i][j] = 0.f;
    }

    const int kv_end = q0 + BQ;
    for (int j0 = 0; j0 < kv_end; j0 += BKV) {
        __syncthreads();
        for (int idx = tid; idx < BKV * (HD_ / 4); idx += 256) {
            int r = idx >> 4;
            int d4 = (idx & 15) * 4;
            float4 kv4 = *reinterpret_cast<const float4*>(kbase + (size_t)(j0 + r) * C3_ + d4);
            Ks[r][d4 + 0] = kv4.x; Ks[r][d4 + 1] = kv4.y;
            Ks[r][d4 + 2] = kv4.z; Ks[r][d4 + 3] = kv4.w;
            float4 vv = *reinterpret_cast<const float4*>(vbase + (size_t)(j0 + r) * C3_ + d4);
            Vs[r][d4 + 0] = vv.x; Vs[r][d4 + 1] = vv.y;
            Vs[r][d4 + 2] = vv.z; Vs[r][d4 + 3] = vv.w;
        }
        __syncthreads();

        float s[8][4];
#pragma unroll
        for (int i = 0; i < 8; i++)
#pragma unroll
            for (int j = 0; j < 4; j++) s[i][j] = 0.f;
#pragma unroll 8
        for (int d = 0; d < HD_; d++) {
            float a[8], bb[4];
#pragma unroll
            for (int i = 0; i < 8; i++) a[i] = Qs[ty * 8 + i][d];
#pragma unroll
            for (int j = 0; j < 4; j++) bb[j] = Ks[tx * 4 + j][d];
#pragma unroll
            for (int i = 0; i < 8; i++)
#pragma unroll
                for (int j = 0; j < 4; j++) s[i][j] += a[i] * bb[j];
        }
        const bool need_mask = (j0 + BKV - 1) > q0;
#pragma unroll
        for (int i = 0; i < 8; i++) {
            const int qi = q0 + ty * 8 + i;
#pragma unroll
            for (int j = 0; j < 4; j++) {
                float val = s[i][j] * 0.125f;
                if (need_mask && (j0 + tx * 4 + j) > qi) val = -1e30f;
                s[i][j] = val;
            }
        }

#pragma unroll
        for (int i = 0; i < 8; i++) {
            float mx = fmaxf(fmaxf(s[i][0], s[i][1]), fmaxf(s[i][2], s[i][3]));
#pragma unroll
            for (int off = 8; off > 0; off >>= 1)
                mx = fmaxf(mx, __shfl_xor_sync(0xffffffffu, mx, off));
            const float mnew = fmaxf(m[i], mx);
            const float alpha = __expf(m[i] - mnew);
            float psum = 0.f;
#pragma unroll
            for (int j = 0; j < 4; j++) {
                float p = __expf(s[i][j] - mnew);
                s[i][j] = p;
                psum += p;
            }
#pragma unroll
            for (int off = 8; off > 0; off >>= 1)
                psum += __shfl_xor_sync(0xffffffffu, psum, off);
            l[i] = l[i] * alpha + psum;
            m[i] = mnew;
#pragma unroll
            for (int j = 0; j < 4; j++) o[i][j] *= alpha;
        }

#pragma unroll
        for (int i = 0; i < 8; i++)
#pragma unroll
            for (int j = 0; j < 4; j++)
                Ps[ty * 8 + i][tx * 4 + j] = s[i][j];
        __syncthreads();

#pragma unroll 8
        for (int j = 0; j < BKV; j++) {
            float a[8], bb[4];
#pragma unroll
            for (int i = 0; i < 8; i++) a[i] = Ps[ty * 8 + i][j];
#pragma unroll
            for (int jj = 0; jj < 4; jj++) bb[jj] = Vs[j][tx * 4 + jj];
#pragma unroll
            for (int i = 0; i < 8; i++)
#pragma unroll
                for (int jj = 0; jj < 4; jj++) o[i][jj] += a[i] * bb[jj];
        }
    }

    float* ybase = y + (size_t)b * T_ * C_ + (size_t)h * HD_;
#pragma unroll
    for (int i = 0; i < 8; i++) {
        const float inv = 1.0f / l[i];
        const size_t row = (size_t)(q0 + ty * 8 + i) * C_;
#pragma unroll
        for (int jj = 0; jj < 4; jj++)
            ybase[row + tx * 4 + jj] = o[i][jj] * inv;
    }
}

// ---------------------------------------------------------------------------
extern "C" void kernel_launch(void* const* d_in, const int* in_sizes, int n_in,
                              void* d_out, int out_size)
{
    const float* x      = (const float*)d_in[0];
    const float* fcos   = (const float*)d_in[1];
    const float* fsin   = (const float*)d_in[2];
    const float* w_attn = (const float*)d_in[3];
    const float* w_proj = (const float*)d_in[4];
    const float* qw     = (const float*)d_in[5];
    const float* kw     = (const float*)d_in[6];
    float* out = (float*)d_out;

    float *qkv, *yb;
    __nv_bfloat16 *xhi, *xlo, *wahi, *walo, *wphi, *wplo, *yhi, *ylo;
    cudaGetSymbolAddress((void**)&qkv,  g_qkv);
    cudaGetSymbolAddress((void**)&yb,   g_y);
    cudaGetSymbolAddress((void**)&xhi,  g_xhi);
    cudaGetSymbolAddress((void**)&xlo,  g_xlo);
    cudaGetSymbolAddress((void**)&wahi, g_wahi);
    cudaGetSymbolAddress((void**)&walo, g_walo);
    cudaGetSymbolAddress((void**)&wphi, g_wphi);
    cudaGetSymbolAddress((void**)&wplo, g_wplo);
    cudaGetSymbolAddress((void**)&yhi,  g_yhi);
    cudaGetSymbolAddress((void**)&ylo,  g_ylo);

    cudaFuncSetAttribute(gemm_mma_split, cudaFuncAttributeMaxDynamicSharedMemorySize, GSMEM);

    // 1) split inputs to (hi, lo) bf16
    {
        int n4 = (M_ * C_) / 4;
        split_f32<<<(n4 + 255) / 256, 256>>>(x, xhi, xlo, n4);
        n4 = (C3_ * C_) / 4;
        split_f32<<<(n4 + 255) / 256, 256>>>(w_attn, wahi, walo, n4);
        n4 = (C_ * C_) / 4;
        split_f32<<<(n4 + 255) / 256, 256>>>(w_proj, wphi, wplo, n4);
    }

    // 2) qkv = x @ w_attn^T  (mma.sync split-bf16)
    {
        dim3 g(C3_ / 128, M_ / 128);
        gemm_mma_split<<<g, 256, GSMEM>>>(xhi, xlo, wahi, walo, qkv, C3_, C_);
    }

    // 3) RMSNorm + RoPE in place
    norm_rope<<<(B_ * T_ * H_) / 8, 256>>>(qkv, fcos, fsin, qw, kw);

    // 4) causal flash attention -> y
    const int flash_smem = (128 * 65 + 64 * 65 + 64 * 65 + 128 * 65) * (int)sizeof(float);
    cudaFuncSetAttribute(flash_fwd, cudaFuncAttributeMaxDynamicSharedMemorySize, flash_smem);
    dim3 g3(T_ / 128, B_ * H_);
    flash_fwd<<<g3, 256, flash_smem>>>(qkv, yb);

    // 5) split y
    {
        int n4 = (M_ * C_) / 4;
        split_f32<<<(n4 + 255) / 256, 256>>>(yb, yhi, ylo, n4);
    }

    // 6) out = y @ w_proj^T  (mma.sync split-bf16)
    {
        dim3 g(C_ / 128, M_ / 128);
        gemm_mma_split<<<g, 256, GSMEM>>>(yhi, ylo, wphi, wplo, out, C_, C_);
    }
}

// round 5
// speedup vs baseline: 3.0014x; 1.9176x over previous
#include <cuda_runtime.h>
#include <cuda_bf16.h>
#include <cstdint>
#include <cstddef>

static constexpr int B_  = 2;
static constexpr int T_  = 2048;
static constexpr int C_  = 1024;
static constexpr int H_  = 16;
static constexpr int HD_ = 64;
static constexpr int C3_ = 3 * C_;
static constexpr int M_  = B_ * T_;      // 4096

// ---------------------------------------------------------------------------
// Scratch (__device__ globals; no allocation allowed)
// ---------------------------------------------------------------------------
__device__ float g_qkv[(size_t)M_ * C3_];                 // 50 MB
__device__ __nv_bfloat16 g_xhi[(size_t)M_ * C_];
__device__ __nv_bfloat16 g_xlo[(size_t)M_ * C_];
__device__ __nv_bfloat16 g_wahi[(size_t)C3_ * C_];
__device__ __nv_bfloat16 g_walo[(size_t)C3_ * C_];
__device__ __nv_bfloat16 g_wphi[(size_t)C_ * C_];
__device__ __nv_bfloat16 g_wplo[(size_t)C_ * C_];
__device__ __nv_bfloat16 g_yhi[(size_t)M_ * C_];
__device__ __nv_bfloat16 g_ylo[(size_t)M_ * C_];
// head-major [B][H][T][64] split operands for flash
__device__ __nv_bfloat16 g_qh[(size_t)M_ * C_];
__device__ __nv_bfloat16 g_ql[(size_t)M_ * C_];
__device__ __nv_bfloat16 g_kh[(size_t)M_ * C_];
__device__ __nv_bfloat16 g_kl[(size_t)M_ * C_];
__device__ __nv_bfloat16 g_vh[(size_t)M_ * C_];
__device__ __nv_bfloat16 g_vl[(size_t)M_ * C_];

// ---------------------------------------------------------------------------
// Helpers (sm_80-level: cp.async, ldmatrix, mma.sync)
// ---------------------------------------------------------------------------
__device__ __forceinline__ uint32_t smem_u32(const void* p) {
    uint32_t a;
    asm("{ .reg .u64 t; cvta.to.shared.u64 t, %1; cvt.u32.u64 %0, t; }" : "=r"(a) : "l"(p));
    return a;
}
#define SWZ128(o) ((o) ^ (((o) >> 3) & 0x70))

__device__ __forceinline__ void cp_async16(uint32_t dst, const void* src) {
    asm volatile("cp.async.cg.shared.global [%0], [%1], 16;" :: "r"(dst), "l"(src));
}
__device__ __forceinline__ void ldsm4(uint32_t& r0, uint32_t& r1, uint32_t& r2, uint32_t& r3,
                                      uint32_t addr) {
    asm volatile("ldmatrix.sync.aligned.m8n8.x4.shared.b16 {%0,%1,%2,%3}, [%4];"
                 : "=r"(r0), "=r"(r1), "=r"(r2), "=r"(r3) : "r"(addr));
}
__device__ __forceinline__ void ldsm4t(uint32_t& r0, uint32_t& r1, uint32_t& r2, uint32_t& r3,
                                       uint32_t addr) {
    asm volatile("ldmatrix.sync.aligned.m8n8.x4.trans.shared.b16 {%0,%1,%2,%3}, [%4];"
                 : "=r"(r0), "=r"(r1), "=r"(r2), "=r"(r3) : "r"(addr));
}
__device__ __forceinline__ void mma16816(float* c, const uint32_t* a, const uint32_t* b) {
    asm volatile(
        "mma.sync.aligned.m16n8k16.row.col.f32.bf16.bf16.f32 "
        "{%0,%1,%2,%3}, {%4,%5,%6,%7}, {%8,%9}, {%0,%1,%2,%3};"
        : "+f"(c[0]), "+f"(c[1]), "+f"(c[2]), "+f"(c[3])
        : "r"(a[0]), "r"(a[1]), "r"(a[2]), "r"(a[3]), "r"(b[0]), "r"(b[1]));
}
__device__ __forceinline__ void split2(float a, float b, uint32_t& hi, uint32_t& lo) {
    __nv_bfloat16 ha = __float2bfloat16_rn(a), hb = __float2bfloat16_rn(b);
    __nv_bfloat162 H(ha, hb);
    __nv_bfloat162 L(__float2bfloat16_rn(a - __bfloat162float(ha)),
                     __float2bfloat16_rn(b - __bfloat162float(hb)));
    hi = *reinterpret_cast<uint32_t*>(&H);
    lo = *reinterpret_cast<uint32_t*>(&L);
}

// ---------------------------------------------------------------------------
// Split fp32 -> (hi, lo) bf16 (for x, w_attn, w_proj)
// ---------------------------------------------------------------------------
__global__ __launch_bounds__(256)
void split_f32(const float* __restrict__ in, __nv_bfloat16* __restrict__ hi,
               __nv_bfloat16* __restrict__ lo, int n4)
{
    int i = blockIdx.x * blockDim.x + threadIdx.x;
    if (i >= n4) return;
    float4 v = reinterpret_cast<const float4*>(in)[i];
    uint32_t h0, l0, h1, l1;
    split2(v.x, v.y, h0, l0);
    split2(v.z, v.w, h1, l1);
    reinterpret_cast<uint32_t*>(hi)[2 * i]     = h0;
    reinterpret_cast<uint32_t*>(hi)[2 * i + 1] = h1;
    reinterpret_cast<uint32_t*>(lo)[2 * i]     = l0;
    reinterpret_cast<uint32_t*>(lo)[2 * i + 1] = l1;
}

// ---------------------------------------------------------------------------
// mma.sync split-bf16 GEMM (NT), 128x128 tile, BK=64, 8 warps, double buffer.
// ---------------------------------------------------------------------------
static constexpr int GSMEM = 65536;

__global__ __launch_bounds__(256, 2)
void gemm_mma_split(const __nv_bfloat16* __restrict__ Ahi,
                    const __nv_bfloat16* __restrict__ Alo,
                    const __nv_bfloat16* __restrict__ Bhi,
                    const __nv_bfloat16* __restrict__ Blo,
                    float* __restrict__ Cout, int N, int K)
{
    extern __shared__ char smem[];
    const uint32_t smem_base = smem_u32(smem);
    const int tid  = threadIdx.x;
    const int lane = tid & 31;
    const int wid  = tid >> 5;
    const int wr = (wid >> 2) * 64;
    const int wc = (wid & 3) * 32;
    const int m0 = blockIdx.y * 128;
    const int n0 = blockIdx.x * 128;

    float acc[4][4][4];
#pragma unroll
    for (int mi = 0; mi < 4; mi++)
#pragma unroll
        for (int ni = 0; ni < 4; ni++)
#pragma unroll
            for (int e = 0; e < 4; e++) acc[mi][ni][e] = 0.f;

    const __nv_bfloat16* Aps[3] = { Ahi, Ahi, Alo };
    const __nv_bfloat16* Bps[3] = { Bhi, Blo, Bhi };
    const int KC = K >> 6;
    const int NC = 3 * KC;

    auto load_chunk = [&](int cg) {
        const int pass = cg / KC;
        const int kc   = cg - pass * KC;
        const __nv_bfloat16* Ab = Aps[pass] + (size_t)m0 * K + kc * 64;
        const __nv_bfloat16* Bb = Bps[pass] + (size_t)n0 * K + kc * 64;
        const uint32_t As = smem_base + (cg & 1) * 16384;
        const uint32_t Bs = smem_base + 32768 + (cg & 1) * 16384;
#pragma unroll
        for (int i = 0; i < 4; i++) {
            const int u = tid + 256 * i;
            const int row = u >> 3, ch = u & 7;
            cp_async16(As + SWZ128(row * 128 + ch * 16), Ab + (size_t)row * K + ch * 8);
            cp_async16(Bs + SWZ128(row * 128 + ch * 16), Bb + (size_t)row * K + ch * 8);
        }
        asm volatile("cp.async.commit_group;");
    };

    load_chunk(0);
    for (int cg = 0; cg < NC; cg++) {
        if (cg + 1 < NC) {
            load_chunk(cg + 1);
            asm volatile("cp.async.wait_group 1;");
        } else {
            asm volatile("cp.async.wait_group 0;");
        }
        __syncthreads();

        const uint32_t As = smem_base + (cg & 1) * 16384;
        const uint32_t Bs = smem_base + 32768 + (cg & 1) * 16384;
#pragma unroll
        for (int ks = 0; ks < 4; ks++) {
            const int k0 = ks * 16;
            uint32_t a[4][4], b[4][2];
#pragma unroll
            for (int mi = 0; mi < 4; mi++) {
                const uint32_t ad = As + SWZ128((wr + mi * 16 + (lane & 15)) * 128 +
                                                (k0 + (lane >> 4) * 8) * 2);
                ldsm4(a[mi][0], a[mi][1], a[mi][2], a[mi][3], ad);
            }
#pragma unroll
            for (int p = 0; p < 2; p++) {
                const int g = lane >> 3;
                const int r = wc + p * 16 + (g >> 1) * 8 + (lane & 7);
                const int cb = (k0 + (g & 1) * 8) * 2;
                const uint32_t bd = Bs + SWZ128(r * 128 + cb);
                ldsm4(b[2 * p][0], b[2 * p][1], b[2 * p + 1][0], b[2 * p + 1][1], bd);
            }
#pragma unroll
            for (int mi = 0; mi < 4; mi++)
#pragma unroll
                for (int ni = 0; ni < 4; ni++)
                    mma16816(acc[mi][ni], a[mi], b[ni]);
        }
        __syncthreads();
    }

#pragma unroll
    for (int mi = 0; mi < 4; mi++) {
        const int m = m0 + wr + mi * 16 + (lane >> 2);
#pragma unroll
        for (int ni = 0; ni < 4; ni++) {
            const int n = n0 + wc + ni * 8 + (lane & 3) * 2;
            *reinterpret_cast<float2*>(Cout + (size_t)m * N + n) =
                make_float2(acc[mi][ni][0], acc[mi][ni][1]);
            *reinterpret_cast<float2*>(Cout + (size_t)(m + 8) * N + n) =
                make_float2(acc[mi][ni][2], acc[mi][ni][3]);
        }
    }
}

// ---------------------------------------------------------------------------
// Fused per-head RMSNorm + RoPE + hi/lo split, writes head-major [B][H][T][64].
// One warp per (bt, h).
// ---------------------------------------------------------------------------
__global__ __launch_bounds__(256)
void norm_rope_split(const float* __restrict__ qkv, const float* __restrict__ cosT,
                     const float* __restrict__ sinT, const float* __restrict__ qw,
                     const float* __restrict__ kw,
                     __nv_bfloat16* __restrict__ qh, __nv_bfloat16* __restrict__ ql,
                     __nv_bfloat16* __restrict__ kh, __nv_bfloat16* __restrict__ kl,
                     __nv_bfloat16* __restrict__ vh, __nv_bfloat16* __restrict__ vl)
{
    const int gw = (blockIdx.x * blockDim.x + threadIdx.x) >> 5;
    const int lane = threadIdx.x & 31;
    const int h = gw & (H_ - 1);
    const int bt = gw >> 4;
    const int t = bt & (T_ - 1);
    const int b = bt >> 11;                         // T_=2048

    const float* qp = qkv + (size_t)bt * C3_ + h * HD_;
    const float* kp = qp + C_;
    const float* vp = qp + 2 * C_;
    const size_t ho = (((size_t)(b * H_ + h) * T_) + t) * HD_ + 2 * lane;
    const float c = cosT[t * (HD_ / 2) + lane];
    const float s = sinT[t * (HD_ / 2) + lane];

    {
        float2 v = *reinterpret_cast<const float2*>(qp + 2 * lane);
        float ss = v.x * v.x + v.y * v.y;
#pragma unroll
        for (int off = 16; off > 0; off >>= 1) ss += __shfl_xor_sync(0xffffffffu, ss, off);
        float rms = rsqrtf(ss * (1.f / HD_) + 1e-6f);
        float x0 = v.x * rms * qw[2 * lane];
        float x1 = v.y * rms * qw[2 * lane + 1];
        float r0 = x0 * c - x1 * s;
        float r1 = x0 * s + x1 * c;
        uint32_t hi, lo;
        split2(r0, r1, hi, lo);
        *reinterpret_cast<uint32_t*>(qh + ho) = hi;
        *reinterpret_cast<uint32_t*>(ql + ho) = lo;
    }
    {
        float2 v = *reinterpret_cast<const float2*>(kp + 2 * lane);
        float ss = v.x * v.x + v.y * v.y;
#pragma unroll
        for (int off = 16; off > 0; off >>= 1) ss += __shfl_xor_sync(0xffffffffu, ss, off);
        float rms = rsqrtf(ss * (1.f / HD_) + 1e-6f);
        float x0 = v.x * rms * kw[2 * lane];
        float x1 = v.y * rms * kw[2 * lane + 1];
        float r0 = x0 * c - x1 * s;
        float r1 = x0 * s + x1 * c;
        uint32_t hi, lo;
        split2(r0, r1, hi, lo);
        *reinterpret_cast<uint32_t*>(kh + ho) = hi;
        *reinterpret_cast<uint32_t*>(kl + ho) = lo;
    }
    {
        float2 v = *reinterpret_cast<const float2*>(vp + 2 * lane);
        uint32_t hi, lo;
        split2(v.x, v.y, hi, lo);
        *reinterpret_cast<uint32_t*>(vh + ho) = hi;
        *reinterpret_cast<uint32_t*>(vl + ho) = lo;
    }
}

// ---------------------------------------------------------------------------
// mma.sync flash attention, causal, split-bf16 (3-pass QK^T, 3-pass PV).
// BQ=128 (8 warps x 16 rows), BKV=64. Writes yhi/ylo bf16 [bt][C] for proj GEMM.
// smem: Qhi,Qlo 16KB each + 2 x (Khi,Klo,Vhi,Vlo 8KB each) = 96 KB.
// ---------------------------------------------------------------------------
static constexpr int FSMEM = 98304;

__global__ __launch_bounds__(256, 2)
void flash_mma(const __nv_bfloat16* __restrict__ qh, const __nv_bfloat16* __restrict__ ql,
               const __nv_bfloat16* __restrict__ kh, const __nv_bfloat16* __restrict__ kl,
               const __nv_bfloat16* __restrict__ vh, const __nv_bfloat16* __restrict__ vl,
               __nv_bfloat16* __restrict__ yhi, __nv_bfloat16* __restrict__ ylo)
{
    extern __shared__ char smem[];
    const uint32_t sb = smem_u32(smem);
    const int tid = threadIdx.x, lane = tid & 31, wid = tid >> 5;
    const int gid = lane >> 2, tig = lane & 3;
    const int bh = blockIdx.y;                 // b*H + h
    const int q0 = (gridDim.x - 1 - blockIdx.x) * 128;   // heavy tiles first
    const size_t head = (size_t)bh * T_ * HD_;

    const uint32_t QHI = sb, QLO = sb + 16384;
    auto KV = [&](int buf, int t) -> uint32_t { return sb + 32768 + buf * 32768 + t * 8192; };

    // initial loads: Q tiles + KV iter 0
    {
#pragma unroll
        for (int i = 0; i < 4; i++) {
            int u = tid + 256 * i, r = u >> 3, ch = u & 7;
            uint32_t so = SWZ128(r * 128 + ch * 16);
            size_t go = head + (size_t)(q0 + r) * HD_ + ch * 8;
            cp_async16(QHI + so, qh + go);
            cp_async16(QLO + so, ql + go);
        }
#pragma unroll
        for (int i = 0; i < 2; i++) {
            int u = tid + 256 * i, r = u >> 3, ch = u & 7;
            uint32_t so = SWZ128(r * 128 + ch * 16);
            size_t go = head + (size_t)r * HD_ + ch * 8;
            cp_async16(KV(0, 0) + so, kh + go);
            cp_async16(KV(0, 1) + so, kl + go);
            cp_async16(KV(0, 2) + so, vh + go);
            cp_async16(KV(0, 3) + so, vl + go);
        }
        asm volatile("cp.async.commit_group;");
    }

    float O[8][4];
#pragma unroll
    for (int nt = 0; nt < 8; nt++)
#pragma unroll
        for (int e = 0; e < 4; e++) O[nt][e] = 0.f;
    float mrow0 = -1e30f, mrow1 = -1e30f, lrow0 = 0.f, lrow1 = 0.f;

    const int warp_top = q0 + wid * 16;
    const int niter = (q0 + 128) / 64;

    for (int it = 0; it < niter; it++) {
        asm volatile("cp.async.wait_group 0;");
        __syncthreads();
        const int cur = it & 1;
        if (it + 1 < niter) {
            const int nxt = 1 - cur;
            const size_t koff = head + (size_t)(it + 1) * 64 * HD_;
#pragma unroll
            for (int i = 0; i < 2; i++) {
                int u = tid + 256 * i, r = u >> 3, ch = u & 7;
                uint32_t so = SWZ128(r * 128 + ch * 16);
                size_t go = koff + (size_t)r * HD_ + ch * 8;
                cp_async16(KV(nxt, 0) + so, kh + go);
                cp_async16(KV(nxt, 1) + so, kl + go);
                cp_async16(KV(nxt, 2) + so, vh + go);
                cp_async16(KV(nxt, 3) + so, vl + go);
            }
            asm volatile("cp.async.commit_group;");
        }

        const int j0 = it * 64;
        if (j0 > warp_top + 15) continue;   // warp fully masked this tile

        // ---- S = scale * (Qhi Khi^T + Qlo Khi^T + Qhi Klo^T) ----
        float S[8][4];
#pragma unroll
        for (int nt = 0; nt < 8; nt++)
#pragma unroll
            for (int e = 0; e < 4; e++) S[nt][e] = 0.f;

        const uint32_t Kb0 = KV(cur, 0), Kb1 = KV(cur, 1);
#pragma unroll
        for (int pass = 0; pass < 3; pass++) {
            const uint32_t Qb = (pass == 1) ? QLO : QHI;
            const uint32_t Kb = (pass == 2) ? Kb1 : Kb0;
#pragma unroll
            for (int ks = 0; ks < 4; ks++) {
                const int k0 = ks * 16;
                uint32_t a[4];
                ldsm4(a[0], a[1], a[2], a[3],
                      Qb + SWZ128((wid * 16 + (lane & 15)) * 128 + (k0 + (lane >> 4) * 8) * 2));
                uint32_t b[8][2];
#pragma unroll
                for (int p = 0; p < 4; p++) {
                    const int g = lane >> 3;
                    const int r = p * 16 + (g >> 1) * 8 + (lane & 7);
                    ldsm4(b[2 * p][0], b[2 * p][1], b[2 * p + 1][0], b[2 * p + 1][1],
                          Kb + SWZ128(r * 128 + (k0 + (g & 1) * 8) * 2));
                }
#pragma unroll
                for (int nt = 0; nt < 8; nt++) mma16816(S[nt], a, b[nt]);
            }
        }

        // ---- scale + causal mask ----
        const int qi0 = warp_top + gid;
        if (j0 + 63 > warp_top) {
#pragma unroll
            for (int nt = 0; nt < 8; nt++)
#pragma unroll
                for (int e = 0; e < 4; e++) {
                    const int kj = j0 + nt * 8 + 2 * tig + (e & 1);
                    const int qi = qi0 + ((e >= 2) ? 8 : 0);
                    S[nt][e] = (kj <= qi) ? S[nt][e] * 0.125f : -1e30f;
                }
        } else {
#pragma unroll
            for (int nt = 0; nt < 8; nt++)
#pragma unroll
                for (int e = 0; e < 4; e++) S[nt][e] *= 0.125f;
        }

        // ---- online softmax (2 rows per thread) ----
        float mx0 = -1e30f, mx1 = -1e30f;
#pragma unroll
        for (int nt = 0; nt < 8; nt++) {
            mx0 = fmaxf(mx0, fmaxf(S[nt][0], S[nt][1]));
            mx1 = fmaxf(mx1, fmaxf(S[nt][2], S[nt][3]));
        }
        mx0 = fmaxf(mx0, __shfl_xor_sync(0xffffffffu, mx0, 1));
        mx0 = fmaxf(mx0, __shfl_xor_sync(0xffffffffu, mx0, 2));
        mx1 = fmaxf(mx1, __shfl_xor_sync(0xffffffffu, mx1, 1));
        mx1 = fmaxf(mx1, __shfl_xor_sync(0xffffffffu, mx1, 2));
        const float mn0 = fmaxf(mrow0, mx0), mn1 = fmaxf(mrow1, mx1);
        const float al0 = __expf(mrow0 - mn0), al1 = __expf(mrow1 - mn1);
        float ps0 = 0.f, ps1 = 0.f;
#pragma unroll
        for (int nt = 0; nt < 8; nt++) {
            S[nt][0] = __expf(S[nt][0] - mn0);
            S[nt][1] = __expf(S[nt][1] - mn0);
            S[nt][2] = __expf(S[nt][2] - mn1);
            S[nt][3] = __expf(S[nt][3] - mn1);
            ps0 += S[nt][0] + S[nt][1];
            ps1 += S[nt][2] + S[nt][3];
        }
        ps0 += __shfl_xor_sync(0xffffffffu, ps0, 1);
        ps0 += __shfl_xor_sync(0xffffffffu, ps0, 2);
        ps1 += __shfl_xor_sync(0xffffffffu, ps1, 1);
        ps1 += __shfl_xor_sync(0xffffffffu, ps1, 2);
        lrow0 = lrow0 * al0 + ps0;
        lrow1 = lrow1 * al1 + ps1;
        mrow0 = mn0;
        mrow1 = mn1;
#pragma unroll
        for (int nt = 0; nt < 8; nt++) {
            O[nt][0] *= al0; O[nt][1] *= al0;
            O[nt][2] *= al1; O[nt][3] *= al1;
        }

        // ---- pack P hi/lo fragments (S acc layout == A frag layout) ----
        uint32_t Phi[4][4], Plo[4][4];
#pragma unroll
        for (int kt = 0; kt < 4; kt++) {
            split2(S[2 * kt][0],     S[2 * kt][1],     Phi[kt][0], Plo[kt][0]);
            split2(S[2 * kt][2],     S[2 * kt][3],     Phi[kt][1], Plo[kt][1]);
            split2(S[2 * kt + 1][0], S[2 * kt + 1][1], Phi[kt][2], Plo[kt][2]);
            split2(S[2 * kt + 1][2], S[2 * kt + 1][3], Phi[kt][3], Plo[kt][3]);
        }

        // ---- O += Phi Vhi + Plo Vhi + Phi Vlo ----
        const uint32_t Vh = KV(cur, 2), Vlb = KV(cur, 3);
#pragma unroll
        for (int ks = 0; ks < 4; ks++) {
            uint32_t vb[8][2];
#pragma unroll
            for (int p = 0; p < 4; p++) {
                const int g = lane >> 3;
                const int r = ks * 16 + (g & 1) * 8 + (lane & 7);
                const int cb = (p * 16 + (g >> 1) * 8) * 2;
                ldsm4t(vb[2 * p][0], vb[2 * p][1], vb[2 * p + 1][0], vb[2 * p + 1][1],
                       Vh + SWZ128(r * 128 + cb));
            }
#pragma unroll
            for (int nt = 0; nt < 8; nt++) mma16816(O[nt], Phi[ks], vb[nt]);
#pragma unroll
            for (int nt = 0; nt < 8; nt++) mma16816(O[nt], Plo[ks], vb[nt]);
#pragma unroll
            for (int p = 0; p < 4; p++) {
                const int g = lane >> 3;
                const int r = ks * 16 + (g & 1) * 8 + (lane & 7);
                const int cb = (p * 16 + (g >> 1) * 8) * 2;
                ldsm4t(vb[2 * p][0], vb[2 * p][1], vb[2 * p + 1][0], vb[2 * p + 1][1],
                       Vlb + SWZ128(r * 128 + cb));
            }
#pragma unroll
            for (int nt = 0; nt < 8; nt++) mma16816(O[nt], Phi[ks], vb[nt]);
        }
    }

    // ---- epilogue: y = O / l, split to bf16 hi/lo, layout [bt][h*64+d] ----
    const float inv0 = 1.0f / lrow0, inv1 = 1.0f / lrow1;
    const int b = bh >> 4, h = bh & 15;
    const size_t row0 = ((size_t)(b * T_ + warp_top + gid)) * C_ + h * HD_;
    const size_t row1 = row0 + (size_t)8 * C_;
#pragma unroll
    for (int nt = 0; nt < 8; nt++) {
        const int col = nt * 8 + 2 * tig;
        uint32_t hi, lo;
        split2(O[nt][0] * inv0, O[nt][1] * inv0, hi, lo);
        *reinterpret_cast<uint32_t*>(yhi + row0 + col) = hi;
        *reinterpret_cast<uint32_t*>(ylo + row0 + col) = lo;
        split2(O[nt][2] * inv1, O[nt][3] * inv1, hi, lo);
        *reinterpret_cast<uint32_t*>(yhi + row1 + col) = hi;
        *reinterpret_cast<uint32_t*>(ylo + row1 + col) = lo;
    }
}

// ---------------------------------------------------------------------------
extern "C" void kernel_launch(void* const* d_in, const int* in_sizes, int n_in,
                              void* d_out, int out_size)
{
    const float* x      = (const float*)d_in[0];
    const float* fcos   = (const float*)d_in[1];
    const float* fsin   = (const float*)d_in[2];
    const float* w_attn = (const float*)d_in[3];
    const float* w_proj = (const float*)d_in[4];
    const float* qw     = (const float*)d_in[5];
    const float* kw     = (const float*)d_in[6];
    float* out = (float*)d_out;

    float* qkv;
    __nv_bfloat16 *xhi, *xlo, *wahi, *walo, *wphi, *wplo, *yhi, *ylo;
    __nv_bfloat16 *qh, *ql, *kh, *kl, *vh, *vl;
    cudaGetSymbolAddress((void**)&qkv,  g_qkv);
    cudaGetSymbolAddress((void**)&xhi,  g_xhi);
    cudaGetSymbolAddress((void**)&xlo,  g_xlo);
    cudaGetSymbolAddress((void**)&wahi, g_wahi);
    cudaGetSymbolAddress((void**)&walo, g_walo);
    cudaGetSymbolAddress((void**)&wphi, g_wphi);
    cudaGetSymbolAddress((void**)&wplo, g_wplo);
    cudaGetSymbolAddress((void**)&yhi,  g_yhi);
    cudaGetSymbolAddress((void**)&ylo,  g_ylo);
    cudaGetSymbolAddress((void**)&qh,   g_qh);
    cudaGetSymbolAddress((void**)&ql,   g_ql);
    cudaGetSymbolAddress((void**)&kh,   g_kh);
    cudaGetSymbolAddress((void**)&kl,   g_kl);
    cudaGetSymbolAddress((void**)&vh,   g_vh);
    cudaGetSymbolAddress((void**)&vl,   g_vl);

    cudaFuncSetAttribute(gemm_mma_split, cudaFuncAttributeMaxDynamicSharedMemorySize, GSMEM);
    cudaFuncSetAttribute(flash_mma, cudaFuncAttributeMaxDynamicSharedMemorySize, FSMEM);

    // 1) split inputs to (hi, lo) bf16
    {
        int n4 = (M_ * C_) / 4;
        split_f32<<<(n4 + 255) / 256, 256>>>(x, xhi, xlo, n4);
        n4 = (C3_ * C_) / 4;
        split_f32<<<(n4 + 255) / 256, 256>>>(w_attn, wahi, walo, n4);
        n4 = (C_ * C_) / 4;
        split_f32<<<(n4 + 255) / 256, 256>>>(w_proj, wphi, wplo, n4);
    }

    // 2) qkv = x @ w_attn^T
    {
        dim3 g(C3_ / 128, M_ / 128);
        gemm_mma_split<<<g, 256, GSMEM>>>(xhi, xlo, wahi, walo, qkv, C3_, C_);
    }

    // 3) RMSNorm + RoPE + split to head-major bf16
    norm_rope_split<<<(B_ * T_ * H_) / 8, 256>>>(qkv, fcos, fsin, qw, kw,
                                                 qh, ql, kh, kl, vh, vl);

    // 4) causal flash attention (tensor-core) -> yhi/ylo
    {
        dim3 g(T_ / 128, B_ * H_);
        flash_mma<<<g, 256, FSMEM>>>(qh, ql, kh, kl, vh, vl, yhi, ylo);
    }

    // 5) out = y @ w_proj^T
    {
        dim3 g(C_ / 128, M_ / 128);
        gemm_mma_split<<<g, 256, GSMEM>>>(yhi, ylo, wphi, wplo, out, C_, C_);
    }
}

// round 6
// speedup vs baseline: 3.1095x; 1.0360x over previous
#include <cuda_runtime.h>
#include <cuda_bf16.h>
#include <cstdint>
#include <cstddef>

static constexpr int B_  = 2;
static constexpr int T_  = 2048;
static constexpr int C_  = 1024;
static constexpr int H_  = 16;
static constexpr int HD_ = 64;
static constexpr int C3_ = 3 * C_;
static constexpr int M_  = B_ * T_;      // 4096

// ---------------------------------------------------------------------------
// Scratch (__device__ globals; no allocation allowed)
// ---------------------------------------------------------------------------
__device__ float g_qkv[(size_t)M_ * C3_];                 // 50 MB
__device__ __nv_bfloat16 g_xhi[(size_t)M_ * C_];
__device__ __nv_bfloat16 g_xlo[(size_t)M_ * C_];
__device__ __nv_bfloat16 g_wahi[(size_t)C3_ * C_];
__device__ __nv_bfloat16 g_walo[(size_t)C3_ * C_];
__device__ __nv_bfloat16 g_wphi[(size_t)C_ * C_];
__device__ __nv_bfloat16 g_wplo[(size_t)C_ * C_];
__device__ __nv_bfloat16 g_yhi[(size_t)M_ * C_];
__device__ __nv_bfloat16 g_ylo[(size_t)M_ * C_];
// head-major [B][H][T][64] split operands for flash
__device__ __nv_bfloat16 g_qh[(size_t)M_ * C_];
__device__ __nv_bfloat16 g_ql[(size_t)M_ * C_];
__device__ __nv_bfloat16 g_kh[(size_t)M_ * C_];
__device__ __nv_bfloat16 g_kl[(size_t)M_ * C_];
__device__ __nv_bfloat16 g_vh[(size_t)M_ * C_];
__device__ __nv_bfloat16 g_vl[(size_t)M_ * C_];

// ---------------------------------------------------------------------------
// Helpers (sm_80-level: cp.async, ldmatrix, mma.sync)
// ---------------------------------------------------------------------------
__device__ __forceinline__ uint32_t smem_u32(const void* p) {
    uint32_t a;
    asm("{ .reg .u64 t; cvta.to.shared.u64 t, %1; cvt.u32.u64 %0, t; }" : "=r"(a) : "l"(p));
    return a;
}
#define SWZ128(o) ((o) ^ (((o) >> 3) & 0x70))

__device__ __forceinline__ void cp_async16(uint32_t dst, const void* src) {
    asm volatile("cp.async.cg.shared.global [%0], [%1], 16;" :: "r"(dst), "l"(src));
}
__device__ __forceinline__ void ldsm4(uint32_t& r0, uint32_t& r1, uint32_t& r2, uint32_t& r3,
                                      uint32_t addr) {
    asm volatile("ldmatrix.sync.aligned.m8n8.x4.shared.b16 {%0,%1,%2,%3}, [%4];"
                 : "=r"(r0), "=r"(r1), "=r"(r2), "=r"(r3) : "r"(addr));
}
__device__ __forceinline__ void ldsm4t(uint32_t& r0, uint32_t& r1, uint32_t& r2, uint32_t& r3,
                                       uint32_t addr) {
    asm volatile("ldmatrix.sync.aligned.m8n8.x4.trans.shared.b16 {%0,%1,%2,%3}, [%4];"
                 : "=r"(r0), "=r"(r1), "=r"(r2), "=r"(r3) : "r"(addr));
}
__device__ __forceinline__ void mma16816(float* c, const uint32_t* a, const uint32_t* b) {
    asm volatile(
        "mma.sync.aligned.m16n8k16.row.col.f32.bf16.bf16.f32 "
        "{%0,%1,%2,%3}, {%4,%5,%6,%7}, {%8,%9}, {%0,%1,%2,%3};"
        : "+f"(c[0]), "+f"(c[1]), "+f"(c[2]), "+f"(c[3])
        : "r"(a[0]), "r"(a[1]), "r"(a[2]), "r"(a[3]), "r"(b[0]), "r"(b[1]));
}
__device__ __forceinline__ void split2(float a, float b, uint32_t& hi, uint32_t& lo) {
    __nv_bfloat16 ha = __float2bfloat16_rn(a), hb = __float2bfloat16_rn(b);
    __nv_bfloat162 H(ha, hb);
    __nv_bfloat162 L(__float2bfloat16_rn(a - __bfloat162float(ha)),
                     __float2bfloat16_rn(b - __bfloat162float(hb)));
    hi = *reinterpret_cast<uint32_t*>(&H);
    lo = *reinterpret_cast<uint32_t*>(&L);
}

// ---------------------------------------------------------------------------
// Split fp32 -> (hi, lo) bf16 (for x, w_attn, w_proj)
// ---------------------------------------------------------------------------
__global__ __launch_bounds__(256)
void split_f32(const float* __restrict__ in, __nv_bfloat16* __restrict__ hi,
               __nv_bfloat16* __restrict__ lo, int n4)
{
    int i = blockIdx.x * blockDim.x + threadIdx.x;
    if (i >= n4) return;
    float4 v = reinterpret_cast<const float4*>(in)[i];
    uint32_t h0, l0, h1, l1;
    split2(v.x, v.y, h0, l0);
    split2(v.z, v.w, h1, l1);
    reinterpret_cast<uint32_t*>(hi)[2 * i]     = h0;
    reinterpret_cast<uint32_t*>(hi)[2 * i + 1] = h1;
    reinterpret_cast<uint32_t*>(lo)[2 * i]     = l0;
    reinterpret_cast<uint32_t*>(lo)[2 * i + 1] = l1;
}

// ---------------------------------------------------------------------------
// mma.sync split-bf16 GEMM (NT), single pass over K with interleaved hi/lo.
// 128x128 tile, BK=32 per chunk; smem row = [hi 64B | lo 64B] (SW128).
// Per k-step: load a_hi,a_lo,b_hi,b_lo fragments once, issue 3 passes:
//   acc += Ahi*Bhi + Alo*Bhi + Ahi*Blo
// 8 warps (2x4, 64x32 each), cp.async double buffer (2 x 32KB).
// ---------------------------------------------------------------------------
static constexpr int GSMEM = 65536;

__global__ __launch_bounds__(256, 2)
void gemm_mma_split(const __nv_bfloat16* __restrict__ Ahi,
                    const __nv_bfloat16* __restrict__ Alo,
                    const __nv_bfloat16* __restrict__ Bhi,
                    const __nv_bfloat16* __restrict__ Blo,
                    float* __restrict__ Cout, int N, int K)
{
    extern __shared__ char smem[];
    const uint32_t smem_base = smem_u32(smem);
    const int tid  = threadIdx.x;
    const int lane = tid & 31;
    const int wid  = tid >> 5;
    const int wr = (wid >> 2) * 64;
    const int wc = (wid & 3) * 32;
    const int m0 = blockIdx.y * 128;
    const int n0 = blockIdx.x * 128;

    float acc[4][4][4];
#pragma unroll
    for (int mi = 0; mi < 4; mi++)
#pragma unroll
        for (int ni = 0; ni < 4; ni++)
#pragma unroll
            for (int e = 0; e < 4; e++) acc[mi][ni][e] = 0.f;

    const int NC = K >> 5;      // 32-wide chunks

    // buffer layout: buf*32768: A tile 16KB, then B tile 16KB.
    auto load_chunk = [&](int cg) {
        const int buf = cg & 1;
        const uint32_t As = smem_base + buf * 32768;
        const uint32_t Bs = As + 16384;
        const int k0 = cg * 32;
#pragma unroll
        for (int i = 0; i < 4; i++) {
            const int u = tid + 256 * i;          // 0..1023
            const int row = u >> 3, ch = u & 7;   // ch 0-3: hi, 4-7: lo
            const __nv_bfloat16* srcA = (ch < 4 ? Ahi : Alo) +
                (size_t)(m0 + row) * K + k0 + (ch & 3) * 8;
            cp_async16(As + SWZ128(row * 128 + ch * 16), srcA);
            const __nv_bfloat16* srcB = (ch < 4 ? Bhi : Blo) +
                (size_t)(n0 + row) * K + k0 + (ch & 3) * 8;
            cp_async16(Bs + SWZ128(row * 128 + ch * 16), srcB);
        }
        asm volatile("cp.async.commit_group;");
    };

    load_chunk(0);
    for (int cg = 0; cg < NC; cg++) {
        if (cg + 1 < NC) {
            load_chunk(cg + 1);
            asm volatile("cp.async.wait_group 1;");
        } else {
            asm volatile("cp.async.wait_group 0;");
        }
        __syncthreads();

        const uint32_t As = smem_base + (cg & 1) * 32768;
        const uint32_t Bs = As + 16384;
#pragma unroll
        for (int ks = 0; ks < 2; ks++) {
            // hi byte-col = ks*32 + (sel)*16 in [0,64); lo = +64
            uint32_t bh[4][2], bl[4][2];
#pragma unroll
            for (int p = 0; p < 2; p++) {
                const int g = lane >> 3;
                const int r = wc + p * 16 + (g >> 1) * 8 + (lane & 7);
                const int cb = ks * 32 + (g & 1) * 16;
                ldsm4(bh[2 * p][0], bh[2 * p][1], bh[2 * p + 1][0], bh[2 * p + 1][1],
                      Bs + SWZ128(r * 128 + cb));
                ldsm4(bl[2 * p][0], bl[2 * p][1], bl[2 * p + 1][0], bl[2 * p + 1][1],
                      Bs + SWZ128(r * 128 + 64 + cb));
            }
#pragma unroll
            for (int mi = 0; mi < 4; mi++) {
                const int r = wr + mi * 16 + (lane & 15);
                const int cb = ks * 32 + (lane >> 4) * 16;
                uint32_t ah[4], al[4];
                ldsm4(ah[0], ah[1], ah[2], ah[3], As + SWZ128(r * 128 + cb));
                ldsm4(al[0], al[1], al[2], al[3], As + SWZ128(r * 128 + 64 + cb));
#pragma unroll
                for (int ni = 0; ni < 4; ni++) {
                    mma16816(acc[mi][ni], ah, bh[ni]);
                    mma16816(acc[mi][ni], al, bh[ni]);
                    mma16816(acc[mi][ni], ah, bl[ni]);
                }
            }
        }
        __syncthreads();
    }

#pragma unroll
    for (int mi = 0; mi < 4; mi++) {
        const int m = m0 + wr + mi * 16 + (lane >> 2);
#pragma unroll
        for (int ni = 0; ni < 4; ni++) {
            const int n = n0 + wc + ni * 8 + (lane & 3) * 2;
            *reinterpret_cast<float2*>(Cout + (size_t)m * N + n) =
                make_float2(acc[mi][ni][0], acc[mi][ni][1]);
            *reinterpret_cast<float2*>(Cout + (size_t)(m + 8) * N + n) =
                make_float2(acc[mi][ni][2], acc[mi][ni][3]);
        }
    }
}

// ---------------------------------------------------------------------------
// Fused per-head RMSNorm + RoPE + hi/lo split, writes head-major [B][H][T][64].
// ---------------------------------------------------------------------------
__global__ __launch_bounds__(256)
void norm_rope_split(const float* __restrict__ qkv, const float* __restrict__ cosT,
                     const float* __restrict__ sinT, const float* __restrict__ qw,
                     const float* __restrict__ kw,
                     __nv_bfloat16* __restrict__ qh, __nv_bfloat16* __restrict__ ql,
                     __nv_bfloat16* __restrict__ kh, __nv_bfloat16* __restrict__ kl,
                     __nv_bfloat16* __restrict__ vh, __nv_bfloat16* __restrict__ vl)
{
    const int gw = (blockIdx.x * blockDim.x + threadIdx.x) >> 5;
    const int lane = threadIdx.x & 31;
    const int h = gw & (H_ - 1);
    const int bt = gw >> 4;
    const int t = bt & (T_ - 1);
    const int b = bt >> 11;

    const float* qp = qkv + (size_t)bt * C3_ + h * HD_;
    const float* kp = qp + C_;
    const float* vp = qp + 2 * C_;
    const size_t ho = (((size_t)(b * H_ + h) * T_) + t) * HD_ + 2 * lane;
    const float c = cosT[t * (HD_ / 2) + lane];
    const float s = sinT[t * (HD_ / 2) + lane];

    {
        float2 v = *reinterpret_cast<const float2*>(qp + 2 * lane);
        float ss = v.x * v.x + v.y * v.y;
#pragma unroll
        for (int off = 16; off > 0; off >>= 1) ss += __shfl_xor_sync(0xffffffffu, ss, off);
        float rms = rsqrtf(ss * (1.f / HD_) + 1e-6f);
        float x0 = v.x * rms * qw[2 * lane];
        float x1 = v.y * rms * qw[2 * lane + 1];
        float r0 = x0 * c - x1 * s;
        float r1 = x0 * s + x1 * c;
        uint32_t hi, lo;
        split2(r0, r1, hi, lo);
        *reinterpret_cast<uint32_t*>(qh + ho) = hi;
        *reinterpret_cast<uint32_t*>(ql + ho) = lo;
    }
    {
        float2 v = *reinterpret_cast<const float2*>(kp + 2 * lane);
        float ss = v.x * v.x + v.y * v.y;
#pragma unroll
        for (int off = 16; off > 0; off >>= 1) ss += __shfl_xor_sync(0xffffffffu, ss, off);
        float rms = rsqrtf(ss * (1.f / HD_) + 1e-6f);
        float x0 = v.x * rms * kw[2 * lane];
        float x1 = v.y * rms * kw[2 * lane + 1];
        float r0 = x0 * c - x1 * s;
        float r1 = x0 * s + x1 * c;
        uint32_t hi, lo;
        split2(r0, r1, hi, lo);
        *reinterpret_cast<uint32_t*>(kh + ho) = hi;
        *reinterpret_cast<uint32_t*>(kl + ho) = lo;
    }
    {
        float2 v = *reinterpret_cast<const float2*>(vp + 2 * lane);
        uint32_t hi, lo;
        split2(v.x, v.y, hi, lo);
        *reinterpret_cast<uint32_t*>(vh + ho) = hi;
        *reinterpret_cast<uint32_t*>(vl + ho) = lo;
    }
}

// ---------------------------------------------------------------------------
// mma.sync flash attention, causal, split-bf16 (unchanged from R5).
// ---------------------------------------------------------------------------
static constexpr int FSMEM = 98304;

__global__ __launch_bounds__(256, 2)
void flash_mma(const __nv_bfloat16* __restrict__ qh, const __nv_bfloat16* __restrict__ ql,
               const __nv_bfloat16* __restrict__ kh, const __nv_bfloat16* __restrict__ kl,
               const __nv_bfloat16* __restrict__ vh, const __nv_bfloat16* __restrict__ vl,
               __nv_bfloat16* __restrict__ yhi, __nv_bfloat16* __restrict__ ylo)
{
    extern __shared__ char smem[];
    const uint32_t sb = smem_u32(smem);
    const int tid = threadIdx.x, lane = tid & 31, wid = tid >> 5;
    const int gid = lane >> 2, tig = lane & 3;
    const int bh = blockIdx.y;
    const int q0 = (gridDim.x - 1 - blockIdx.x) * 128;
    const size_t head = (size_t)bh * T_ * HD_;

    const uint32_t QHI = sb, QLO = sb + 16384;
    auto KV = [&](int buf, int t) -> uint32_t { return sb + 32768 + buf * 32768 + t * 8192; };

    {
#pragma unroll
        for (int i = 0; i < 4; i++) {
            int u = tid + 256 * i, r = u >> 3, ch = u & 7;
            uint32_t so = SWZ128(r * 128 + ch * 16);
            size_t go = head + (size_t)(q0 + r) * HD_ + ch * 8;
            cp_async16(QHI + so, qh + go);
            cp_async16(QLO + so, ql + go);
        }
#pragma unroll
        for (int i = 0; i < 2; i++) {
            int u = tid + 256 * i, r = u >> 3, ch = u & 7;
            uint32_t so = SWZ128(r * 128 + ch * 16);
            size_t go = head + (size_t)r * HD_ + ch * 8;
            cp_async16(KV(0, 0) + so, kh + go);
            cp_async16(KV(0, 1) + so, kl + go);
            cp_async16(KV(0, 2) + so, vh + go);
            cp_async16(KV(0, 3) + so, vl + go);
        }
        asm volatile("cp.async.commit_group;");
    }

    float O[8][4];
#pragma unroll
    for (int nt = 0; nt < 8; nt++)
#pragma unroll
        for (int e = 0; e < 4; e++) O[nt][e] = 0.f;
    float mrow0 = -1e30f, mrow1 = -1e30f, lrow0 = 0.f, lrow1 = 0.f;

    const int warp_top = q0 + wid * 16;
    const int niter = (q0 + 128) / 64;

    for (int it = 0; it < niter; it++) {
        asm volatile("cp.async.wait_group 0;");
        __syncthreads();
        const int cur = it & 1;
        if (it + 1 < niter) {
            const int nxt = 1 - cur;
            const size_t koff = head + (size_t)(it + 1) * 64 * HD_;
#pragma unroll
            for (int i = 0; i < 2; i++) {
                int u = tid + 256 * i, r = u >> 3, ch = u & 7;
                uint32_t so = SWZ128(r * 128 + ch * 16);
                size_t go = koff + (size_t)r * HD_ + ch * 8;
                cp_async16(KV(nxt, 0) + so, kh + go);
                cp_async16(KV(nxt, 1) + so, kl + go);
                cp_async16(KV(nxt, 2) + so, vh + go);
                cp_async16(KV(nxt, 3) + so, vl + go);
            }
            asm volatile("cp.async.commit_group;");
        }

        const int j0 = it * 64;
        if (j0 > warp_top + 15) continue;

        float S[8][4];
#pragma unroll
        for (int nt = 0; nt < 8; nt++)
#pragma unroll
            for (int e = 0; e < 4; e++) S[nt][e] = 0.f;

        const uint32_t Kb0 = KV(cur, 0), Kb1 = KV(cur, 1);
#pragma unroll
        for (int pass = 0; pass < 3; pass++) {
            const uint32_t Qb = (pass == 1) ? QLO : QHI;
            const uint32_t Kb = (pass == 2) ? Kb1 : Kb0;
#pragma unroll
            for (int ks = 0; ks < 4; ks++) {
                const int k0 = ks * 16;
                uint32_t a[4];
                ldsm4(a[0], a[1], a[2], a[3],
                      Qb + SWZ128((wid * 16 + (lane & 15)) * 128 + (k0 + (lane >> 4) * 8) * 2));
                uint32_t b[8][2];
#pragma unroll
                for (int p = 0; p < 4; p++) {
                    const int g = lane >> 3;
                    const int r = p * 16 + (g >> 1) * 8 + (lane & 7);
                    ldsm4(b[2 * p][0], b[2 * p][1], b[2 * p + 1][0], b[2 * p + 1][1],
                          Kb + SWZ128(r * 128 + (k0 + (g & 1) * 8) * 2));
                }
#pragma unroll
                for (int nt = 0; nt < 8; nt++) mma16816(S[nt], a, b[nt]);
            }
        }

        const int qi0 = warp_top + gid;
        if (j0 + 63 > warp_top) {
#pragma unroll
            for (int nt = 0; nt < 8; nt++)
#pragma unroll
                for (int e = 0; e < 4; e++) {
                    const int kj = j0 + nt * 8 + 2 * tig + (e & 1);
                    const int qi = qi0 + ((e >= 2) ? 8 : 0);
                    S[nt][e] = (kj <= qi) ? S[nt][e] * 0.125f : -1e30f;
                }
        } else {
#pragma unroll
            for (int nt = 0; nt < 8; nt++)
#pragma unroll
                for (int e = 0; e < 4; e++) S[nt][e] *= 0.125f;
        }

        float mx0 = -1e30f, mx1 = -1e30f;
#pragma unroll
        for (int nt = 0; nt < 8; nt++) {
            mx0 = fmaxf(mx0, fmaxf(S[nt][0], S[nt][1]));
            mx1 = fmaxf(mx1, fmaxf(S[nt][2], S[nt][3]));
        }
        mx0 = fmaxf(mx0, __shfl_xor_sync(0xffffffffu, mx0, 1));
        mx0 = fmaxf(mx0, __shfl_xor_sync(0xffffffffu, mx0, 2));
        mx1 = fmaxf(mx1, __shfl_xor_sync(0xffffffffu, mx1, 1));
        mx1 = fmaxf(mx1, __shfl_xor_sync(0xffffffffu, mx1, 2));
        const float mn0 = fmaxf(mrow0, mx0), mn1 = fmaxf(mrow1, mx1);
        const float al0 = __expf(mrow0 - mn0), al1 = __expf(mrow1 - mn1);
        float ps0 = 0.f, ps1 = 0.f;
#pragma unroll
        for (int nt = 0; nt < 8; nt++) {
            S[nt][0] = __expf(S[nt][0] - mn0);
            S[nt][1] = __expf(S[nt][1] - mn0);
            S[nt][2] = __expf(S[nt][2] - mn1);
            S[nt][3] = __expf(S[nt][3] - mn1);
            ps0 += S[nt][0] + S[nt][1];
            ps1 += S[nt][2] + S[nt][3];
        }
        ps0 += __shfl_xor_sync(0xffffffffu, ps0, 1);
        ps0 += __shfl_xor_sync(0xffffffffu, ps0, 2);
        ps1 += __shfl_xor_sync(0xffffffffu, ps1, 1);
        ps1 += __shfl_xor_sync(0xffffffffu, ps1, 2);
        lrow0 = lrow0 * al0 + ps0;
        lrow1 = lrow1 * al1 + ps1;
        mrow0 = mn0;
        mrow1 = mn1;
#pragma unroll
        for (int nt = 0; nt < 8; nt++) {
            O[nt][0] *= al0; O[nt][1] *= al0;
            O[nt][2] *= al1; O[nt][3] *= al1;
        }

        uint32_t Phi[4][4], Plo[4][4];
#pragma unroll
        for (int kt = 0; kt < 4; kt++) {
            split2(S[2 * kt][0],     S[2 * kt][1],     Phi[kt][0], Plo[kt][0]);
            split2(S[2 * kt][2],     S[2 * kt][3],     Phi[kt][1], Plo[kt][1]);
            split2(S[2 * kt + 1][0], S[2 * kt + 1][1], Phi[kt][2], Plo[kt][2]);
            split2(S[2 * kt + 1][2], S[2 * kt + 1][3], Phi[kt][3], Plo[kt][3]);
        }

        const uint32_t Vh = KV(cur, 2), Vlb = KV(cur, 3);
#pragma unroll
        for (int ks = 0; ks < 4; ks++) {
            uint32_t vb[8][2];
#pragma unroll
            for (int p = 0; p < 4; p++) {
                const int g = lane >> 3;
                const int r = ks * 16 + (g & 1) * 8 + (lane & 7);
                const int cb = (p * 16 + (g >> 1) * 8) * 2;
                ldsm4t(vb[2 * p][0], vb[2 * p][1], vb[2 * p + 1][0], vb[2 * p + 1][1],
                       Vh + SWZ128(r * 128 + cb));
            }
#pragma unroll
            for (int nt = 0; nt < 8; nt++) mma16816(O[nt], Phi[ks], vb[nt]);
#pragma unroll
            for (int nt = 0; nt < 8; nt++) mma16816(O[nt], Plo[ks], vb[nt]);
#pragma unroll
            for (int p = 0; p < 4; p++) {
                const int g = lane >> 3;
                const int r = ks * 16 + (g & 1) * 8 + (lane & 7);
                const int cb = (p * 16 + (g >> 1) * 8) * 2;
                ldsm4t(vb[2 * p][0], vb[2 * p][1], vb[2 * p + 1][0], vb[2 * p + 1][1],
                       Vlb + SWZ128(r * 128 + cb));
            }
#pragma unroll
            for (int nt = 0; nt < 8; nt++) mma16816(O[nt], Phi[ks], vb[nt]);
        }
    }

    const float inv0 = 1.0f / lrow0, inv1 = 1.0f / lrow1;
    const int b = bh >> 4, h = bh & 15;
    const size_t row0 = ((size_t)(b * T_ + warp_top + gid)) * C_ + h * HD_;
    const size_t row1 = row0 + (size_t)8 * C_;
#pragma unroll
    for (int nt = 0; nt < 8; nt++) {
        const int col = nt * 8 + 2 * tig;
        uint32_t hi, lo;
        split2(O[nt][0] * inv0, O[nt][1] * inv0, hi, lo);
        *reinterpret_cast<uint32_t*>(yhi + row0 + col) = hi;
        *reinterpret_cast<uint32_t*>(ylo + row0 + col) = lo;
        split2(O[nt][2] * inv1, O[nt][3] * inv1, hi, lo);
        *reinterpret_cast<uint32_t*>(yhi + row1 + col) = hi;
        *reinterpret_cast<uint32_t*>(ylo + row1 + col) = lo;
    }
}

// ---------------------------------------------------------------------------
extern "C" void kernel_launch(void* const* d_in, const int* in_sizes, int n_in,
                              void* d_out, int out_size)
{
    const float* x      = (const float*)d_in[0];
    const float* fcos   = (const float*)d_in[1];
    const float* fsin   = (const float*)d_in[2];
    const float* w_attn = (const float*)d_in[3];
    const float* w_proj = (const float*)d_in[4];
    const float* qw     = (const float*)d_in[5];
    const float* kw     = (const float*)d_in[6];
    float* out = (float*)d_out;

    float* qkv;
    __nv_bfloat16 *xhi, *xlo, *wahi, *walo, *wphi, *wplo, *yhi, *ylo;
    __nv_bfloat16 *qh, *ql, *kh, *kl, *vh, *vl;
    cudaGetSymbolAddress((void**)&qkv,  g_qkv);
    cudaGetSymbolAddress((void**)&xhi,  g_xhi);
    cudaGetSymbolAddress((void**)&xlo,  g_xlo);
    cudaGetSymbolAddress((void**)&wahi, g_wahi);
    cudaGetSymbolAddress((void**)&walo, g_walo);
    cudaGetSymbolAddress((void**)&wphi, g_wphi);
    cudaGetSymbolAddress((void**)&wplo, g_wplo);
    cudaGetSymbolAddress((void**)&yhi,  g_yhi);
    cudaGetSymbolAddress((void**)&ylo,  g_ylo);
    cudaGetSymbolAddress((void**)&qh,   g_qh);
    cudaGetSymbolAddress((void**)&ql,   g_ql);
    cudaGetSymbolAddress((void**)&kh,   g_kh);
    cudaGetSymbolAddress((void**)&kl,   g_kl);
    cudaGetSymbolAddress((void**)&vh,   g_vh);
    cudaGetSymbolAddress((void**)&vl,   g_vl);

    cudaFuncSetAttribute(gemm_mma_split, cudaFuncAttributeMaxDynamicSharedMemorySize, GSMEM);
    cudaFuncSetAttribute(flash_mma, cudaFuncAttributeMaxDynamicSharedMemorySize, FSMEM);

    // 1) split inputs to (hi, lo) bf16
    {
        int n4 = (M_ * C_) / 4;
        split_f32<<<(n4 + 255) / 256, 256>>>(x, xhi, xlo, n4);
        n4 = (C3_ * C_) / 4;
        split_f32<<<(n4 + 255) / 256, 256>>>(w_attn, wahi, walo, n4);
        n4 = (C_ * C_) / 4;
        split_f32<<<(n4 + 255) / 256, 256>>>(w_proj, wphi, wplo, n4);
    }

    // 2) qkv = x @ w_attn^T
    {
        dim3 g(C3_ / 128, M_ / 128);
        gemm_mma_split<<<g, 256, GSMEM>>>(xhi, xlo, wahi, walo, qkv, C3_, C_);
    }

    // 3) RMSNorm + RoPE + split to head-major bf16
    norm_rope_split<<<(B_ * T_ * H_) / 8, 256>>>(qkv, fcos, fsin, qw, kw,
                                                 qh, ql, kh, kl, vh, vl);

    // 4) causal flash attention (tensor-core) -> yhi/ylo
    {
        dim3 g(T_ / 128, B_ * H_);
        flash_mma<<<g, 256, FSMEM>>>(qh, ql, kh, kl, vh, vl, yhi, ylo);
    }

    // 5) out = y @ w_proj^T
    {
        dim3 g(C_ / 128, M_ / 128);
        gemm_mma_split<<<g, 256, GSMEM>>>(yhi, ylo, wphi, wplo, out, C_, C_);
    }
}